// round 9
// baseline (speedup 1.0000x reference)
#include <cuda_runtime.h>
#include <math.h>

// Problem constants
#define BB    4        // batch
#define SS    16       // seq len
#define HH    512      // hidden
#define G3    1536     // 3*H
#define CD    256
#define SD    256
#define FLAT  65792    // C*T*F
#define DIN   66304    // CD+SD+FLAT
#define KS    32       // split-K slices over FLAT
#define SLICE4 514     // float4s per slice (2056 floats); 32*2056 = 65792
#define NIH  (KS*(G3/32))   // 1536 ih blocks (32 rows each)
#define NHH  (G3/16)        // 96 hh blocks (16 rows each)
#define NBLK (NIH+NHH)      // 1632 blocks in k_step

// Scratch (no allocations allowed -> __device__ globals)
__device__ __align__(16) float g_A[BB*SS*G3];     // content/style/b_ih part of gi
__device__ __align__(16) float g_part[KS*BB*G3];  // split-K partials, layout [sl][b][r]
__device__ __align__(16) float g_gh[BB*G3];       // W_hh @ h, layout [b][r]
__device__ __align__(16) float g_h[2][BB*HH];     // recurrent state, double buffered
__device__ unsigned g_ctr[SS];                    // last-block tickets, one per step

// ---------------------------------------------------------------------------
__global__ void k_init() {
    for (int i = threadIdx.x; i < BB*HH; i += blockDim.x) g_h[0][i] = 0.f;
    if (threadIdx.x < SS) g_ctr[threadIdx.x] = 0u;
}

// A[bs][r] = b_ih[r] + W_ih[r,0:256]@content[b,s] + W_ih[r,256:512]@style[b]
__global__ void k_precompute_A(const float* __restrict__ W_ih,
                               const float* __restrict__ b_ih,
                               const float* __restrict__ content,
                               const float* __restrict__ style) {
    __shared__ float sw[CD + SD];
    int r = blockIdx.x;
    const float* wr = W_ih + (size_t)r * DIN;
    for (int i = threadIdx.x; i < CD + SD; i += 64) sw[i] = wr[i];
    __syncthreads();

    int bs = threadIdx.x;          // 0..63 = b*16+s
    int b  = bs >> 4;
    const float* c  = content + (size_t)bs * CD;
    const float* st = style   + (size_t)b  * SD;
    float acc = 0.f;
    #pragma unroll 8
    for (int j = 0; j < CD; j++) acc += sw[j] * c[j];
    #pragma unroll 8
    for (int j = 0; j < SD; j++) acc += sw[CD + j] * st[j];
    g_A[bs * G3 + r] = acc + b_ih[r];
}

// ---------------------------------------------------------------------------
// Fused per-step kernel:
//   blocks [0, NIH):      split-K gemv of W_ih's prev-columns (the 403 MB stream)
//   blocks [NIH, NBLK):   W_hh @ h_prev (3 MB)
//   last block to finish: GRU gate update (reads g_A/g_part/g_gh, writes g_h[wr])
__global__ void __launch_bounds__(256) k_step(
    const float* __restrict__ W_ih, const float* __restrict__ W_hh,
    const float* __restrict__ b_hh,
    const float* __restrict__ x0, long bstride, int s)
{
    __shared__ float4 sx[4*SLICE4];     // 32.9 KB (hh path reuses as h buffer)
    __shared__ int s_last;
    int bid  = blockIdx.x;
    int w    = threadIdx.x >> 5, lane = threadIdx.x & 31;
    int rd   = s & 1;

    if (bid < NIH) {
        // ---- big gemv: slice sl, rows [rblk*32, rblk*32+32) ----
        int sl = bid / (G3/32), rblk = bid % (G3/32);
        #pragma unroll
        for (int b = 0; b < 4; b++) {
            const float4* xb = (const float4*)(x0 + (size_t)b * bstride) + (size_t)sl * SLICE4;
            for (int j = threadIdx.x; j < SLICE4; j += 256) sx[b*SLICE4 + j] = xb[j];
        }
        __syncthreads();

        int r0 = rblk * 32 + w * 4;
        const float4* wp0 = (const float4*)(W_ih + (size_t)(r0  ) * DIN + (CD+SD)) + (size_t)sl * SLICE4;
        const float4* wp1 = (const float4*)(W_ih + (size_t)(r0+1) * DIN + (CD+SD)) + (size_t)sl * SLICE4;
        const float4* wp2 = (const float4*)(W_ih + (size_t)(r0+2) * DIN + (CD+SD)) + (size_t)sl * SLICE4;
        const float4* wp3 = (const float4*)(W_ih + (size_t)(r0+3) * DIN + (CD+SD)) + (size_t)sl * SLICE4;

        float a[4][4] = {};
        #pragma unroll 2
        for (int j = lane; j < SLICE4; j += 32) {
            float4 u0 = wp0[j], u1 = wp1[j], u2 = wp2[j], u3 = wp3[j];
            #pragma unroll
            for (int b = 0; b < 4; b++) {
                float4 x = sx[b*SLICE4 + j];
                a[0][b] += u0.x*x.x + u0.y*x.y + u0.z*x.z + u0.w*x.w;
                a[1][b] += u1.x*x.x + u1.y*x.y + u1.z*x.z + u1.w*x.w;
                a[2][b] += u2.x*x.x + u2.y*x.y + u2.z*x.z + u2.w*x.w;
                a[3][b] += u3.x*x.x + u3.y*x.y + u3.z*x.z + u3.w*x.w;
            }
        }
        #pragma unroll
        for (int r = 0; r < 4; r++)
            #pragma unroll
            for (int b = 0; b < 4; b++)
                #pragma unroll
                for (int o = 16; o; o >>= 1)
                    a[r][b] += __shfl_down_sync(0xffffffffu, a[r][b], o);
        if (lane == 0) {
            #pragma unroll
            for (int b = 0; b < 4; b++) {
                float4 v = make_float4(a[0][b], a[1][b], a[2][b], a[3][b]);
                ((float4*)g_part)[(((size_t)sl*4 + b) * G3 + r0) >> 2] = v;  // coalesced line per block
            }
        }
    } else {
        // ---- W_hh gemv: rows [idx*16, idx*16+16), 2 rows per warp ----
        int idx = bid - NIH;
        float* sh = (float*)sx;
        for (int t = threadIdx.x; t < BB*HH; t += 256) sh[t] = g_h[rd][t];
        __syncthreads();

        int r0 = idx * 16 + w * 2;
        const float4* v0 = (const float4*)(W_hh + (size_t)(r0  ) * HH);
        const float4* v1 = (const float4*)(W_hh + (size_t)(r0+1) * HH);
        float a0[4] = {}, a1[4] = {};
        #pragma unroll
        for (int q = 0; q < 4; q++) {
            int j = lane + q * 32;
            float4 u0 = v0[j], u1 = v1[j];
            #pragma unroll
            for (int b = 0; b < 4; b++) {
                float4 h = ((const float4*)sh)[b*128 + j];
                a0[b] += u0.x*h.x + u0.y*h.y + u0.z*h.z + u0.w*h.w;
                a1[b] += u1.x*h.x + u1.y*h.y + u1.z*h.z + u1.w*h.w;
            }
        }
        #pragma unroll
        for (int b = 0; b < 4; b++)
            #pragma unroll
            for (int o = 16; o; o >>= 1) {
                a0[b] += __shfl_down_sync(0xffffffffu, a0[b], o);
                a1[b] += __shfl_down_sync(0xffffffffu, a1[b], o);
            }
        if (lane == 0) {
            #pragma unroll
            for (int b = 0; b < 4; b++) {
                g_gh[b*G3 + r0    ] = a0[b];
                g_gh[b*G3 + r0 + 1] = a1[b];
            }
        }
    }

    // ---- last-block gate (threadfence reduction pattern) ----
    __threadfence();
    __syncthreads();
    if (threadIdx.x == 0)
        s_last = (atomicAdd(&g_ctr[s], 1u) == NBLK - 1);
    __syncthreads();
    if (s_last) {
        int wr = rd ^ 1;
        for (int t = threadIdx.x; t < BB*HH; t += 256) {
            int b = t >> 9, i = t & (HH-1);
            size_t abase = (size_t)(b*SS + s) * G3 + i;
            float gr = g_A[abase], gz = g_A[abase + HH], gn = g_A[abase + 2*HH];
            #pragma unroll 8
            for (int k = 0; k < KS; k++) {
                const float* p = g_part + ((size_t)k*4 + b) * G3 + i;
                gr += p[0]; gz += p[HH]; gn += p[2*HH];
            }
            float hr = g_gh[b*G3 + i       ] + b_hh[i       ];
            float hz = g_gh[b*G3 + i +   HH] + b_hh[i +   HH];
            float hn = g_gh[b*G3 + i + 2*HH] + b_hh[i + 2*HH];

            float rg = 1.f / (1.f + expf(-(gr + hr)));
            float zg = 1.f / (1.f + expf(-(gz + hz)));
            float ng = tanhf(gn + rg * hn);
            g_h[wr][t] = (1.f - zg) * ng + zg * g_h[rd][t];
        }
    }
}

// ---------------------------------------------------------------------------
// out[b][s][f] = b_proj[f] + W_proj[f,:] @ h[b].  4 rows per warp, h in smem.
__global__ void __launch_bounds__(256) k_proj(
    const float* __restrict__ W_proj, const float* __restrict__ b_proj,
    float* __restrict__ out, int s)
{
    __shared__ float sh[BB*HH];
    int wr = (s & 1) ^ 1;
    for (int t = threadIdx.x; t < BB*HH; t += 256) sh[t] = g_h[wr][t];
    __syncthreads();

    int w = threadIdx.x >> 5, lane = threadIdx.x & 31;
    int f0 = blockIdx.x * 32 + w * 4;
    float a[4][4] = {};
    #pragma unroll
    for (int q = 0; q < 4; q++) {
        int j = lane + q * 32;
        float4 u0 = ((const float4*)(W_proj + (size_t)(f0  ) * HH))[j];
        float4 u1 = ((const float4*)(W_proj + (size_t)(f0+1) * HH))[j];
        float4 u2 = ((const float4*)(W_proj + (size_t)(f0+2) * HH))[j];
        float4 u3 = ((const float4*)(W_proj + (size_t)(f0+3) * HH))[j];
        #pragma unroll
        for (int b = 0; b < 4; b++) {
            float4 h = ((const float4*)sh)[b*128 + j];
            a[0][b] += u0.x*h.x + u0.y*h.y + u0.z*h.z + u0.w*h.w;
            a[1][b] += u1.x*h.x + u1.y*h.y + u1.z*h.z + u1.w*h.w;
            a[2][b] += u2.x*h.x + u2.y*h.y + u2.z*h.z + u2.w*h.w;
            a[3][b] += u3.x*h.x + u3.y*h.y + u3.z*h.z + u3.w*h.w;
        }
    }
    #pragma unroll
    for (int r = 0; r < 4; r++)
        #pragma unroll
        for (int b = 0; b < 4; b++)
            #pragma unroll
            for (int o = 16; o; o >>= 1)
                a[r][b] += __shfl_down_sync(0xffffffffu, a[r][b], o);
    if (lane == 0) {
        #pragma unroll
        for (int r = 0; r < 4; r++) {
            float bp = b_proj[f0 + r];
            #pragma unroll
            for (int b = 0; b < 4; b++)
                out[(size_t)(b*SS + s) * FLAT + f0 + r] = a[r][b] + bp;
        }
    }
}

// ---------------------------------------------------------------------------
extern "C" void kernel_launch(void* const* d_in, const int* in_sizes, int n_in,
                              void* d_out, int out_size) {
    const float* content = (const float*)d_in[0];   // (B,S,CD)
    const float* style   = (const float*)d_in[1];   // (B,SD)
    const float* start   = (const float*)d_in[2];   // (FLAT,)
    const float* W_ih    = (const float*)d_in[3];   // (3H, DIN)
    const float* W_hh    = (const float*)d_in[4];   // (3H, H)
    const float* b_ih    = (const float*)d_in[5];
    const float* b_hh    = (const float*)d_in[6];
    const float* W_proj  = (const float*)d_in[7];   // (FLAT, H)
    const float* b_proj  = (const float*)d_in[8];
    float* out = (float*)d_out;                     // (B,S,FLAT) viewed flat

    k_init<<<1, 1024>>>();
    k_precompute_A<<<G3, 64>>>(W_ih, b_ih, content, style);

    for (int s = 0; s < SS; s++) {
        const float* x0;
        long bstride;
        if (s == 0) { x0 = start; bstride = 0; }            // prev0 = start_token broadcast
        else { x0 = out + (size_t)(s - 1) * FLAT; bstride = (long)SS * FLAT; }

        k_step<<<NBLK, 256>>>(W_ih, W_hh, b_hh, x0, bstride, s);  // ih + hh + gate
        k_proj<<<FLAT/32, 256>>>(W_proj, b_proj, out, s);         // 135 MB stream
    }
}

// round 12
// speedup vs baseline: 1.0072x; 1.0072x over previous
#include <cuda_runtime.h>
#include <math.h>

// Problem constants
#define BB    4        // batch
#define SS    16       // seq len
#define HH    512      // hidden
#define G3    1536     // 3*H
#define CD    256
#define SD    256
#define FLAT  65792    // C*T*F
#define DIN   66304    // CD+SD+FLAT
#define KS    32       // split-K slices over FLAT
#define SLICE4 514     // float4s per slice (2056 floats); 32*2056 = 65792
#define NIH  (KS*(G3/32))   // 1536 ih blocks (32 rows each)
#define NHH  (G3/16)        // 96 hh blocks (16 rows each)
#define NBLK (NIH+NHH)      // 1632 blocks in k_step

// Scratch (no allocations allowed -> __device__ globals)
__device__ __align__(16) float g_A[BB*SS*G3];     // content/style/b_ih part of gi
__device__ __align__(16) float g_part[KS*BB*G3];  // split-K partials, layout [sl][b][r]
__device__ __align__(16) float g_gh[BB*G3];       // W_hh @ h, layout [b][r]
__device__ __align__(16) float g_h[2][BB*HH];     // recurrent state, double buffered
__device__ unsigned g_ctr[SS];                    // last-block tickets, one per step

// ---------------------------------------------------------------------------
__global__ void k_init() {
    for (int i = threadIdx.x; i < BB*HH; i += blockDim.x) g_h[0][i] = 0.f;
    if (threadIdx.x < SS) g_ctr[threadIdx.x] = 0u;
}

// A[bs][r] = b_ih[r] + W_ih[r,0:256]@content[b,s] + W_ih[r,256:512]@style[b]
__global__ void k_precompute_A(const float* __restrict__ W_ih,
                               const float* __restrict__ b_ih,
                               const float* __restrict__ content,
                               const float* __restrict__ style) {
    __shared__ float sw[CD + SD];
    int r = blockIdx.x;
    const float* wr = W_ih + (size_t)r * DIN;
    for (int i = threadIdx.x; i < CD + SD; i += 64) sw[i] = wr[i];
    __syncthreads();

    int bs = threadIdx.x;          // 0..63 = b*16+s
    int b  = bs >> 4;
    const float* c  = content + (size_t)bs * CD;
    const float* st = style   + (size_t)b  * SD;
    float acc = 0.f;
    #pragma unroll 8
    for (int j = 0; j < CD; j++) acc += sw[j] * c[j];
    #pragma unroll 8
    for (int j = 0; j < SD; j++) acc += sw[CD + j] * st[j];
    g_A[bs * G3 + r] = acc + b_ih[r];
}

// ---------------------------------------------------------------------------
// Fused per-step kernel:
//   blocks [0, NIH):      split-K gemv of W_ih's prev-columns (the 403 MB stream)
//   blocks [NIH, NBLK):   W_hh @ h_prev (3 MB)
//   last block to finish: GRU gate update (reads g_A/g_part/g_gh, writes g_h[wr])
__global__ void __launch_bounds__(256) k_step(
    const float* __restrict__ W_ih, const float* __restrict__ W_hh,
    const float* __restrict__ b_hh,
    const float* __restrict__ x0, long bstride, int s)
{
    __shared__ float4 sx[4*SLICE4];     // 32.9 KB (hh path reuses as h buffer)
    __shared__ int s_last;
    int bid  = blockIdx.x;
    int w    = threadIdx.x >> 5, lane = threadIdx.x & 31;
    int rd   = s & 1;

    if (bid < NIH) {
        // ---- big gemv: slice sl, rows [rblk*32, rblk*32+32) ----
        int sl = bid / (G3/32), rblk = bid % (G3/32);
        #pragma unroll
        for (int b = 0; b < 4; b++) {
            const float4* xb = (const float4*)(x0 + (size_t)b * bstride) + (size_t)sl * SLICE4;
            for (int j = threadIdx.x; j < SLICE4; j += 256) sx[b*SLICE4 + j] = xb[j];
        }
        __syncthreads();

        int r0 = rblk * 32 + w * 4;
        const float4* wp0 = (const float4*)(W_ih + (size_t)(r0  ) * DIN + (CD+SD)) + (size_t)sl * SLICE4;
        const float4* wp1 = (const float4*)(W_ih + (size_t)(r0+1) * DIN + (CD+SD)) + (size_t)sl * SLICE4;
        const float4* wp2 = (const float4*)(W_ih + (size_t)(r0+2) * DIN + (CD+SD)) + (size_t)sl * SLICE4;
        const float4* wp3 = (const float4*)(W_ih + (size_t)(r0+3) * DIN + (CD+SD)) + (size_t)sl * SLICE4;

        float a[4][4] = {};
        #pragma unroll 2
        for (int j = lane; j < SLICE4; j += 32) {
            float4 u0 = wp0[j], u1 = wp1[j], u2 = wp2[j], u3 = wp3[j];
            #pragma unroll
            for (int b = 0; b < 4; b++) {
                float4 x = sx[b*SLICE4 + j];
                a[0][b] += u0.x*x.x + u0.y*x.y + u0.z*x.z + u0.w*x.w;
                a[1][b] += u1.x*x.x + u1.y*x.y + u1.z*x.z + u1.w*x.w;
                a[2][b] += u2.x*x.x + u2.y*x.y + u2.z*x.z + u2.w*x.w;
                a[3][b] += u3.x*x.x + u3.y*x.y + u3.z*x.z + u3.w*x.w;
            }
        }
        #pragma unroll
        for (int r = 0; r < 4; r++)
            #pragma unroll
            for (int b = 0; b < 4; b++)
                #pragma unroll
                for (int o = 16; o; o >>= 1)
                    a[r][b] += __shfl_down_sync(0xffffffffu, a[r][b], o);
        if (lane == 0) {
            #pragma unroll
            for (int b = 0; b < 4; b++) {
                float4 v = make_float4(a[0][b], a[1][b], a[2][b], a[3][b]);
                ((float4*)g_part)[(((size_t)sl*4 + b) * G3 + r0) >> 2] = v;  // coalesced line per block
            }
        }
    } else {
        // ---- W_hh gemv: rows [idx*16, idx*16+16), 2 rows per warp ----
        int idx = bid - NIH;
        float* sh = (float*)sx;
        for (int t = threadIdx.x; t < BB*HH; t += 256) sh[t] = g_h[rd][t];
        __syncthreads();

        int r0 = idx * 16 + w * 2;
        const float4* v0 = (const float4*)(W_hh + (size_t)(r0  ) * HH);
        const float4* v1 = (const float4*)(W_hh + (size_t)(r0+1) * HH);
        float a0[4] = {}, a1[4] = {};
        #pragma unroll
        for (int q = 0; q < 4; q++) {
            int j = lane + q * 32;
            float4 u0 = v0[j], u1 = v1[j];
            #pragma unroll
            for (int b = 0; b < 4; b++) {
                float4 h = ((const float4*)sh)[b*128 + j];
                a0[b] += u0.x*h.x + u0.y*h.y + u0.z*h.z + u0.w*h.w;
                a1[b] += u1.x*h.x + u1.y*h.y + u1.z*h.z + u1.w*h.w;
            }
        }
        #pragma unroll
        for (int b = 0; b < 4; b++)
            #pragma unroll
            for (int o = 16; o; o >>= 1) {
                a0[b] += __shfl_down_sync(0xffffffffu, a0[b], o);
                a1[b] += __shfl_down_sync(0xffffffffu, a1[b], o);
            }
        if (lane == 0) {
            #pragma unroll
            for (int b = 0; b < 4; b++) {
                g_gh[b*G3 + r0    ] = a0[b];
                g_gh[b*G3 + r0 + 1] = a1[b];
            }
        }
    }

    // ---- last-block gate (threadfence reduction pattern) ----
    __threadfence();
    __syncthreads();
    if (threadIdx.x == 0)
        s_last = (atomicAdd(&g_ctr[s], 1u) == NBLK - 1);
    __syncthreads();
    if (s_last) {
        int wr = rd ^ 1;
        for (int t = threadIdx.x; t < BB*HH; t += 256) {
            int b = t >> 9, i = t & (HH-1);
            size_t abase = (size_t)(b*SS + s) * G3 + i;
            float gr = g_A[abase], gz = g_A[abase + HH], gn = g_A[abase + 2*HH];
            #pragma unroll 8
            for (int k = 0; k < KS; k++) {
                const float* p = g_part + ((size_t)k*4 + b) * G3 + i;
                gr += p[0]; gz += p[HH]; gn += p[2*HH];
            }
            float hr = g_gh[b*G3 + i       ] + b_hh[i       ];
            float hz = g_gh[b*G3 + i +   HH] + b_hh[i +   HH];
            float hn = g_gh[b*G3 + i + 2*HH] + b_hh[i + 2*HH];

            float rg = 1.f / (1.f + expf(-(gr + hr)));
            float zg = 1.f / (1.f + expf(-(gz + hz)));
            float ng = tanhf(gn + rg * hn);
            g_h[wr][t] = (1.f - zg) * ng + zg * g_h[rd][t];
        }
    }
}

// ---------------------------------------------------------------------------
// out[b][s][f] = b_proj[f] + W_proj[f,:] @ h[b].  4 rows per warp, h in smem.
__global__ void __launch_bounds__(256) k_proj(
    const float* __restrict__ W_proj, const float* __restrict__ b_proj,
    float* __restrict__ out, int s)
{
    __shared__ float sh[BB*HH];
    int wr = (s & 1) ^ 1;
    for (int t = threadIdx.x; t < BB*HH; t += 256) sh[t] = g_h[wr][t];
    __syncthreads();

    int w = threadIdx.x >> 5, lane = threadIdx.x & 31;
    int f0 = blockIdx.x * 32 + w * 4;
    float a[4][4] = {};
    #pragma unroll
    for (int q = 0; q < 4; q++) {
        int j = lane + q * 32;
        float4 u0 = ((const float4*)(W_proj + (size_t)(f0  ) * HH))[j];
        float4 u1 = ((const float4*)(W_proj + (size_t)(f0+1) * HH))[j];
        float4 u2 = ((const float4*)(W_proj + (size_t)(f0+2) * HH))[j];
        float4 u3 = ((const float4*)(W_proj + (size_t)(f0+3) * HH))[j];
        #pragma unroll
        for (int b = 0; b < 4; b++) {
            float4 h = ((const float4*)sh)[b*128 + j];
            a[0][b] += u0.x*h.x + u0.y*h.y + u0.z*h.z + u0.w*h.w;
            a[1][b] += u1.x*h.x + u1.y*h.y + u1.z*h.z + u1.w*h.w;
            a[2][b] += u2.x*h.x + u2.y*h.y + u2.z*h.z + u2.w*h.w;
            a[3][b] += u3.x*h.x + u3.y*h.y + u3.z*h.z + u3.w*h.w;
        }
    }
    #pragma unroll
    for (int r = 0; r < 4; r++)
        #pragma unroll
        for (int b = 0; b < 4; b++)
            #pragma unroll
            for (int o = 16; o; o >>= 1)
                a[r][b] += __shfl_down_sync(0xffffffffu, a[r][b], o);
    if (lane == 0) {
        #pragma unroll
        for (int r = 0; r < 4; r++) {
            float bp = b_proj[f0 + r];
            #pragma unroll
            for (int b = 0; b < 4; b++)
                out[(size_t)(b*SS + s) * FLAT + f0 + r] = a[r][b] + bp;
        }
    }
}

// ---------------------------------------------------------------------------
extern "C" void kernel_launch(void* const* d_in, const int* in_sizes, int n_in,
                              void* d_out, int out_size) {
    const float* content = (const float*)d_in[0];   // (B,S,CD)
    const float* style   = (const float*)d_in[1];   // (B,SD)
    const float* start   = (const float*)d_in[2];   // (FLAT,)
    const float* W_ih    = (const float*)d_in[3];   // (3H, DIN)
    const float* W_hh    = (const float*)d_in[4];   // (3H, H)
    const float* b_ih    = (const float*)d_in[5];
    const float* b_hh    = (const float*)d_in[6];
    const float* W_proj  = (const float*)d_in[7];   // (FLAT, H)
    const float* b_proj  = (const float*)d_in[8];
    float* out = (float*)d_out;                     // (B,S,FLAT) viewed flat

    k_init<<<1, 1024>>>();
    k_precompute_A<<<G3, 64>>>(W_ih, b_ih, content, style);

    for (int s = 0; s < SS; s++) {
        const float* x0;
        long bstride;
        if (s == 0) { x0 = start; bstride = 0; }            // prev0 = start_token broadcast
        else { x0 = out + (size_t)(s - 1) * FLAT; bstride = (long)SS * FLAT; }

        k_step<<<NBLK, 256>>>(W_ih, W_hh, b_hh, x0, bstride, s);  // ih + hh + gate
        k_proj<<<FLAT/32, 256>>>(W_proj, b_proj, out, s);         // 135 MB stream
    }
}